// round 1
// baseline (speedup 1.0000x reference)
#include <cuda_runtime.h>
#include <cuda_bf16.h>

// Problem constants
#define Bz 8
#define Tz 1024
#define Cz 768
#define NHz 12
#define HDz 64
#define Mz (Bz * Tz)          // 8192
#define N_QKV (3 * Cz)        // 2304

// Scratch in device globals (no allocations allowed)
__device__ float g_qkv[(size_t)Mz * N_QKV];   // [8192, 2304]
__device__ float g_att[(size_t)Mz * Cz];      // [8192, 768]

// ---------------------------------------------------------------------------
// SGEMM: C[M,N] = A[M,K] @ B[K,N] + bias[N]
// 128x128 tile, BK=8, 256 threads, 8x8 micro-tile per thread.
// M, N multiples of 128; K multiple of 8 (holds for 768).
// ---------------------------------------------------------------------------
__global__ __launch_bounds__(256)
void sgemm_bias(const float* __restrict__ A, const float* __restrict__ B,
                const float* __restrict__ bias, float* __restrict__ C,
                int M, int N, int K) {
    __shared__ float As[8][128];
    __shared__ float Bs[8][128];

    const int tid = threadIdx.x;
    const int bm = blockIdx.y * 128;
    const int bn = blockIdx.x * 128;

    // A tile load mapping: thread -> (row, 4-wide k chunk)
    const int arow = tid >> 1;
    const int acol = (tid & 1) * 4;
    // B tile load mapping: thread -> (k row, 4-wide n chunk)
    const int brow = tid >> 5;
    const int bcol = (tid & 31) * 4;

    const float* Aptr = A + (size_t)(bm + arow) * K + acol;
    const float* Bptr = B + (size_t)brow * N + bn + bcol;

    const int ty = tid >> 4;   // 0..15
    const int tx = tid & 15;   // 0..15

    float acc[8][8];
#pragma unroll
    for (int i = 0; i < 8; i++)
#pragma unroll
        for (int j = 0; j < 8; j++) acc[i][j] = 0.0f;

    for (int k0 = 0; k0 < K; k0 += 8) {
        float4 av = *(const float4*)(Aptr + k0);
        float4 bv = *(const float4*)(Bptr + (size_t)k0 * N);
        As[acol + 0][arow] = av.x;
        As[acol + 1][arow] = av.y;
        As[acol + 2][arow] = av.z;
        As[acol + 3][arow] = av.w;
        *(float4*)&Bs[brow][bcol] = bv;
        __syncthreads();

#pragma unroll
        for (int k = 0; k < 8; k++) {
            float4 a0 = *(const float4*)&As[k][ty * 8];
            float4 a1 = *(const float4*)&As[k][ty * 8 + 4];
            float4 b0 = *(const float4*)&Bs[k][tx * 8];
            float4 b1 = *(const float4*)&Bs[k][tx * 8 + 4];
            float a[8] = {a0.x, a0.y, a0.z, a0.w, a1.x, a1.y, a1.z, a1.w};
            float b[8] = {b0.x, b0.y, b0.z, b0.w, b1.x, b1.y, b1.z, b1.w};
#pragma unroll
            for (int i = 0; i < 8; i++)
#pragma unroll
                for (int j = 0; j < 8; j++) acc[i][j] += a[i] * b[j];
        }
        __syncthreads();
    }

#pragma unroll
    for (int i = 0; i < 8; i++) {
        int row = bm + ty * 8 + i;
        float* cp = C + (size_t)row * N + bn + tx * 8;
#pragma unroll
        for (int j = 0; j < 8; j += 4) {
            float4 o;
            o.x = acc[i][j + 0] + bias[bn + tx * 8 + j + 0];
            o.y = acc[i][j + 1] + bias[bn + tx * 8 + j + 1];
            o.z = acc[i][j + 2] + bias[bn + tx * 8 + j + 2];
            o.w = acc[i][j + 3] + bias[bn + tx * 8 + j + 3];
            *(float4*)(cp + j) = o;
        }
    }
}

// ---------------------------------------------------------------------------
// Causal flash attention. One CTA per (b, h, 64-row q-tile).
// 256 threads: thread (r = tid/4, cg = tid%4).
// S-phase columns:  cS = cg + 4*j   (conflict-free Ks reads, stride 68)
// O-phase columns:  cO = cg*16 + j  (float4 Vs reads, conflict-free)
// P shared through smem so the two phases can use different column maps.
// ---------------------------------------------------------------------------
#define ATS 68  // smem row stride (floats)

__global__ __launch_bounds__(256)
void attn_kernel(const float* __restrict__ qkv, float* __restrict__ y) {
    extern __shared__ float sm[];
    float* Qs = sm;                 // 64*ATS
    float* Ks = Qs + 64 * ATS;
    float* Vs = Ks + 64 * ATS;
    float* Ps = Vs + 64 * ATS;

    const int tid = threadIdx.x;
    const int bh = blockIdx.y;
    const int b = bh / NHz;
    const int h = bh % NHz;
    const int q0 = blockIdx.x * 64;

    const float* qbase = qkv + (size_t)b * Tz * N_QKV + h * HDz;

    // Load + pre-scale Q tile (1/sqrt(64) = 0.125)
    for (int i = tid; i < 64 * 64; i += 256) {
        int r = i >> 6, c = i & 63;
        Qs[r * ATS + c] = qbase[(size_t)(q0 + r) * N_QKV + c] * 0.125f;
    }

    const int r = tid >> 2;   // q row within tile (0..63)
    const int cg = tid & 3;   // column group (0..3)

    float m = -1e30f, l = 0.0f;
    float acc[16];
#pragma unroll
    for (int j = 0; j < 16; j++) acc[j] = 0.0f;

    const int ntiles = blockIdx.x + 1;  // causal: key tiles 0..q-tile
    for (int kt = 0; kt < ntiles; kt++) {
        const int k0 = kt * 64;
        __syncthreads();  // prior O-phase done reading Vs
        for (int i = tid; i < 64 * 64; i += 256) {
            int rr = i >> 6, c = i & 63;
            const float* kb = qbase + (size_t)(k0 + rr) * N_QKV;
            Ks[rr * ATS + c] = kb[Cz + c];
            Vs[rr * ATS + c] = kb[2 * Cz + c];
        }
        __syncthreads();

        // S = Q K^T for this thread's 16 columns (cg + 4j)
        float s[16];
#pragma unroll
        for (int j = 0; j < 16; j++) s[j] = 0.0f;
        for (int d4 = 0; d4 < 16; d4++) {
            float4 q = *(const float4*)&Qs[r * ATS + d4 * 4];
#pragma unroll
            for (int j = 0; j < 16; j++) {
                float4 kv = *(const float4*)&Ks[(cg + 4 * j) * ATS + d4 * 4];
                s[j] += q.x * kv.x + q.y * kv.y + q.z * kv.z + q.w * kv.w;
            }
        }

        // Causal mask (only diagonal tile)
        if (kt == ntiles - 1) {
            int q_idx = q0 + r;
#pragma unroll
            for (int j = 0; j < 16; j++) {
                int k_idx = k0 + cg + 4 * j;
                if (k_idx > q_idx) s[j] = -1e30f;
            }
        }

        // Online softmax (row stats shared across the 4 cg threads)
        float mt = s[0];
#pragma unroll
        for (int j = 1; j < 16; j++) mt = fmaxf(mt, s[j]);
        mt = fmaxf(mt, __shfl_xor_sync(0xffffffffu, mt, 1));
        mt = fmaxf(mt, __shfl_xor_sync(0xffffffffu, mt, 2));
        float mnew = fmaxf(m, mt);
        float alpha = __expf(m - mnew);

        float ls = 0.0f;
#pragma unroll
        for (int j = 0; j < 16; j++) {
            float p = __expf(s[j] - mnew);
            ls += p;
            Ps[r * ATS + cg + 4 * j] = p;
        }
        ls += __shfl_xor_sync(0xffffffffu, ls, 1);
        ls += __shfl_xor_sync(0xffffffffu, ls, 2);
        l = l * alpha + ls;
        m = mnew;
#pragma unroll
        for (int j = 0; j < 16; j++) acc[j] *= alpha;
        __syncthreads();  // Ps fully written

        // O += P V for this thread's 16 columns (cg*16 + j)
        for (int k = 0; k < 64; k++) {
            float p = Ps[r * ATS + k];
#pragma unroll
            for (int j4 = 0; j4 < 4; j4++) {
                float4 v = *(const float4*)&Vs[k * ATS + cg * 16 + j4 * 4];
                acc[j4 * 4 + 0] += p * v.x;
                acc[j4 * 4 + 1] += p * v.y;
                acc[j4 * 4 + 2] += p * v.z;
                acc[j4 * 4 + 3] += p * v.w;
            }
        }
    }

    float inv = 1.0f / l;
    float* yb = y + (size_t)(b * Tz + q0 + r) * Cz + h * HDz + cg * 16;
#pragma unroll
    for (int j4 = 0; j4 < 4; j4++) {
        float4 o;
        o.x = acc[j4 * 4 + 0] * inv;
        o.y = acc[j4 * 4 + 1] * inv;
        o.z = acc[j4 * 4 + 2] * inv;
        o.w = acc[j4 * 4 + 3] * inv;
        *(float4*)&yb[j4 * 4] = o;
    }
}

// ---------------------------------------------------------------------------
// Launch
// ---------------------------------------------------------------------------
extern "C" void kernel_launch(void* const* d_in, const int* in_sizes, int n_in,
                              void* d_out, int out_size) {
    const float* x      = (const float*)d_in[0];
    const float* W_attn = (const float*)d_in[1];
    const float* b_attn = (const float*)d_in[2];
    const float* W_proj = (const float*)d_in[3];
    const float* b_proj = (const float*)d_in[4];
    float* out = (float*)d_out;

    float* qkv = nullptr;
    float* att = nullptr;
    cudaGetSymbolAddress((void**)&qkv, g_qkv);
    cudaGetSymbolAddress((void**)&att, g_att);

    const int attn_smem = 4 * 64 * ATS * (int)sizeof(float);  // 69632 B
    cudaFuncSetAttribute(attn_kernel, cudaFuncAttributeMaxDynamicSharedMemorySize,
                         attn_smem);

    // 1) QKV projection: [8192,768] @ [768,2304]
    sgemm_bias<<<dim3(N_QKV / 128, Mz / 128), 256>>>(x, W_attn, b_attn, qkv,
                                                     Mz, N_QKV, Cz);
    // 2) Causal attention
    attn_kernel<<<dim3(Tz / 64, Bz * NHz), 256, attn_smem>>>(qkv, att);
    // 3) Output projection: [8192,768] @ [768,768]
    sgemm_bias<<<dim3(Cz / 128, Mz / 128), 256>>>(att, W_proj, b_proj, out,
                                                  Mz, Cz, Cz);
}

// round 3
// speedup vs baseline: 1.5822x; 1.5822x over previous
#include <cuda_runtime.h>
#include <cuda_bf16.h>

// Problem constants
#define Bz 8
#define Tz 1024
#define Cz 768
#define NHz 12
#define HDz 64
#define Mz (Bz * Tz)          // 8192
#define N_QKV (3 * Cz)        // 2304

// Scratch in device globals (no allocations allowed)
__device__ float g_qkv[(size_t)Mz * N_QKV];   // [8192, 2304]
__device__ float g_att[(size_t)Mz * Cz];      // [8192, 768]

// ---------------------------------------------------------------------------
// SGEMM: C[M,N] = A[M,K] @ B[K,N] + bias[N]   (unchanged from R0)
// ---------------------------------------------------------------------------
__global__ __launch_bounds__(256)
void sgemm_bias(const float* __restrict__ A, const float* __restrict__ B,
                const float* __restrict__ bias, float* __restrict__ C,
                int M, int N, int K) {
    __shared__ float As[8][128];
    __shared__ float Bs[8][128];

    const int tid = threadIdx.x;
    const int bm = blockIdx.y * 128;
    const int bn = blockIdx.x * 128;

    const int arow = tid >> 1;
    const int acol = (tid & 1) * 4;
    const int brow = tid >> 5;
    const int bcol = (tid & 31) * 4;

    const float* Aptr = A + (size_t)(bm + arow) * K + acol;
    const float* Bptr = B + (size_t)brow * N + bn + bcol;

    const int ty = tid >> 4;
    const int tx = tid & 15;

    float acc[8][8];
#pragma unroll
    for (int i = 0; i < 8; i++)
#pragma unroll
        for (int j = 0; j < 8; j++) acc[i][j] = 0.0f;

    for (int k0 = 0; k0 < K; k0 += 8) {
        float4 av = *(const float4*)(Aptr + k0);
        float4 bv = *(const float4*)(Bptr + (size_t)k0 * N);
        As[acol + 0][arow] = av.x;
        As[acol + 1][arow] = av.y;
        As[acol + 2][arow] = av.z;
        As[acol + 3][arow] = av.w;
        *(float4*)&Bs[brow][bcol] = bv;
        __syncthreads();

#pragma unroll
        for (int k = 0; k < 8; k++) {
            float4 a0 = *(const float4*)&As[k][ty * 8];
            float4 a1 = *(const float4*)&As[k][ty * 8 + 4];
            float4 b0 = *(const float4*)&Bs[k][tx * 8];
            float4 b1 = *(const float4*)&Bs[k][tx * 8 + 4];
            float a[8] = {a0.x, a0.y, a0.z, a0.w, a1.x, a1.y, a1.z, a1.w};
            float b[8] = {b0.x, b0.y, b0.z, b0.w, b1.x, b1.y, b1.z, b1.w};
#pragma unroll
            for (int i = 0; i < 8; i++)
#pragma unroll
                for (int j = 0; j < 8; j++) acc[i][j] += a[i] * b[j];
        }
        __syncthreads();
    }

#pragma unroll
    for (int i = 0; i < 8; i++) {
        int row = bm + ty * 8 + i;
        float* cp = C + (size_t)row * N + bn + tx * 8;
#pragma unroll
        for (int j = 0; j < 8; j += 4) {
            float4 o;
            o.x = acc[i][j + 0] + bias[bn + tx * 8 + j + 0];
            o.y = acc[i][j + 1] + bias[bn + tx * 8 + j + 1];
            o.z = acc[i][j + 2] + bias[bn + tx * 8 + j + 2];
            o.w = acc[i][j + 3] + bias[bn + tx * 8 + j + 3];
            *(float4*)(cp + j) = o;
        }
    }
}

// ---------------------------------------------------------------------------
// Causal flash attention, register-blocked, XOR-swizzled smem.
// One CTA per (b, h, 64-row q-tile). 256 threads as a 16x16 grid.
// Thread (ty,tx) owns rows ty*4..+3, cols tx*4..+3 of each 64x64 tile.
// Tile layout: float4 (row, c4f) stored at row*64 + ((c4f ^ (row>>2)) & 15)*4.
// Row stride 64 floats (16B-aligned); strided-row LDS.128 is conflict-free
// because (c4f ^ tx) mod 8 permutes the 8 bank groups within each quarter.
// ---------------------------------------------------------------------------
__device__ __forceinline__ int sw4(int row, int c4f) {
    return row * 64 + (((c4f) ^ (row >> 2)) & 15) * 4;
}

__device__ __forceinline__ float dot4(float4 a, float4 b) {
    return a.x * b.x + a.y * b.y + a.z * b.z + a.w * b.w;
}

__global__ __launch_bounds__(256)
void attn_kernel(const float* __restrict__ qkv, float* __restrict__ y) {
    extern __shared__ float sm[];
    float* Qs = sm;                 // 64*64
    float* Ks = Qs + 64 * 64;
    float* Vs = Ks + 64 * 64;
    float* Ps = Vs + 64 * 64;

    const int tid = threadIdx.x;
    const int bh = blockIdx.y;
    const int b = bh / NHz;
    const int h = bh % NHz;
    const int q0 = blockIdx.x * 64;

    const float* qbase = qkv + (size_t)b * Tz * N_QKV + h * HDz;

    const int ty = tid >> 4;   // 0..15
    const int tx = tid & 15;   // 0..15
    const int ty4 = ty * 4;
    const int tx4 = tx * 4;

    // Load + pre-scale Q tile (1/sqrt(64) = 0.125)
#pragma unroll
    for (int t = 0; t < 4; t++) {
        int idx = tid + t * 256;          // 0..1023
        int rr = idx >> 4;
        int c4f = idx & 15;
        float4 v = *(const float4*)(qbase + (size_t)(q0 + rr) * N_QKV + c4f * 4);
        v.x *= 0.125f; v.y *= 0.125f; v.z *= 0.125f; v.w *= 0.125f;
        *(float4*)&Qs[sw4(rr, c4f)] = v;
    }

    float m[4], l[4];
    float acc[4][4];
#pragma unroll
    for (int i = 0; i < 4; i++) {
        m[i] = -1e30f; l[i] = 0.0f;
#pragma unroll
        for (int j = 0; j < 4; j++) acc[i][j] = 0.0f;
    }

    const int ntiles = blockIdx.x + 1;  // causal: key tiles 0..q-tile
    for (int kt = 0; kt < ntiles; kt++) {
        const int k0 = kt * 64;
        __syncthreads();  // prior O-phase done reading Vs/Ps
#pragma unroll
        for (int t = 0; t < 4; t++) {
            int idx = tid + t * 256;
            int rr = idx >> 4;
            int c4f = idx & 15;
            const float* kb = qbase + (size_t)(k0 + rr) * N_QKV + c4f * 4;
            *(float4*)&Ks[sw4(rr, c4f)] = *(const float4*)(kb + Cz);
            *(float4*)&Vs[sw4(rr, c4f)] = *(const float4*)(kb + 2 * Cz);
        }
        __syncthreads();

        // ---- S = Q K^T : 4x4 micro-tile, k step 4 ----
        float s[4][4];
#pragma unroll
        for (int i = 0; i < 4; i++)
#pragma unroll
            for (int j = 0; j < 4; j++) s[i][j] = 0.0f;

#pragma unroll 4
        for (int k4f = 0; k4f < 16; k4f++) {
            float4 qf[4], kf[4];
#pragma unroll
            for (int i = 0; i < 4; i++)
                qf[i] = *(const float4*)&Qs[sw4(ty4 + i, k4f)];
#pragma unroll
            for (int j = 0; j < 4; j++)
                kf[j] = *(const float4*)&Ks[sw4(tx4 + j, k4f)];
#pragma unroll
            for (int i = 0; i < 4; i++)
#pragma unroll
                for (int j = 0; j < 4; j++) s[i][j] += dot4(qf[i], kf[j]);
        }

        // ---- causal mask (diagonal tile only) ----
        if (kt == ntiles - 1) {
#pragma unroll
            for (int i = 0; i < 4; i++) {
                int q_idx = q0 + ty4 + i;
#pragma unroll
                for (int j = 0; j < 4; j++) {
                    if (k0 + tx4 + j > q_idx) s[i][j] = -1e30f;
                }
            }
        }

        // ---- online softmax (row stats across the 16-lane tx group) ----
#pragma unroll
        for (int i = 0; i < 4; i++) {
            float mt = fmaxf(fmaxf(s[i][0], s[i][1]), fmaxf(s[i][2], s[i][3]));
            mt = fmaxf(mt, __shfl_xor_sync(0xffffffffu, mt, 1));
            mt = fmaxf(mt, __shfl_xor_sync(0xffffffffu, mt, 2));
            mt = fmaxf(mt, __shfl_xor_sync(0xffffffffu, mt, 4));
            mt = fmaxf(mt, __shfl_xor_sync(0xffffffffu, mt, 8));
            float mnew = fmaxf(m[i], mt);
            float alpha = __expf(m[i] - mnew);

            float4 p;
            p.x = __expf(s[i][0] - mnew);
            p.y = __expf(s[i][1] - mnew);
            p.z = __expf(s[i][2] - mnew);
            p.w = __expf(s[i][3] - mnew);
            float ls = p.x + p.y + p.z + p.w;
            ls += __shfl_xor_sync(0xffffffffu, ls, 1);
            ls += __shfl_xor_sync(0xffffffffu, ls, 2);
            ls += __shfl_xor_sync(0xffffffffu, ls, 4);
            ls += __shfl_xor_sync(0xffffffffu, ls, 8);

            *(float4*)&Ps[sw4(ty4 + i, tx)] = p;
            l[i] = l[i] * alpha + ls;
            m[i] = mnew;
#pragma unroll
            for (int j = 0; j < 4; j++) acc[i][j] *= alpha;
        }
        __syncthreads();  // Ps fully written

        // ---- O += P V : 4x4 micro-tile, k step 4 ----
#pragma unroll 4
        for (int k4f = 0; k4f < 16; k4f++) {
            float4 pf[4], vf[4];
#pragma unroll
            for (int i = 0; i < 4; i++)
                pf[i] = *(const float4*)&Ps[sw4(ty4 + i, k4f)];
#pragma unroll
            for (int kk = 0; kk < 4; kk++)
                vf[kk] = *(const float4*)&Vs[sw4(k4f * 4 + kk, tx)];
#pragma unroll
            for (int i = 0; i < 4; i++) {
                acc[i][0] += pf[i].x * vf[0].x + pf[i].y * vf[1].x
                           + pf[i].z * vf[2].x + pf[i].w * vf[3].x;
                acc[i][1] += pf[i].x * vf[0].y + pf[i].y * vf[1].y
                           + pf[i].z * vf[2].y + pf[i].w * vf[3].y;
                acc[i][2] += pf[i].x * vf[0].z + pf[i].y * vf[1].z
                           + pf[i].z * vf[2].z + pf[i].w * vf[3].z;
                acc[i][3] += pf[i].x * vf[0].w + pf[i].y * vf[1].w
                           + pf[i].z * vf[2].w + pf[i].w * vf[3].w;
            }
        }
    }

    // ---- epilogue ----
#pragma unroll
    for (int i = 0; i < 4; i++) {
        float inv = 1.0f / l[i];
        float4 o;
        o.x = acc[i][0] * inv;
        o.y = acc[i][1] * inv;
        o.z = acc[i][2] * inv;
        o.w = acc[i][3] * inv;
        float* yb = y + (size_t)(b * Tz + q0 + ty4 + i) * Cz + h * HDz + tx4;
        *(float4*)yb = o;
    }
}

// ---------------------------------------------------------------------------
// Launch
// ---------------------------------------------------------------------------
extern "C" void kernel_launch(void* const* d_in, const int* in_sizes, int n_in,
                              void* d_out, int out_size) {
    const float* x      = (const float*)d_in[0];
    const float* W_attn = (const float*)d_in[1];
    const float* b_attn = (const float*)d_in[2];
    const float* W_proj = (const float*)d_in[3];
    const float* b_proj = (const float*)d_in[4];
    float* out = (float*)d_out;

    float* qkv = nullptr;
    float* att = nullptr;
    cudaGetSymbolAddress((void**)&qkv, g_qkv);
    cudaGetSymbolAddress((void**)&att, g_att);

    const int attn_smem = 4 * 64 * 64 * (int)sizeof(float);  // 65536 B
    cudaFuncSetAttribute(attn_kernel, cudaFuncAttributeMaxDynamicSharedMemorySize,
                         attn_smem);

    // 1) QKV projection: [8192,768] @ [768,2304]
    sgemm_bias<<<dim3(N_QKV / 128, Mz / 128), 256>>>(x, W_attn, b_attn, qkv,
                                                     Mz, N_QKV, Cz);
    // 2) Causal attention
    attn_kernel<<<dim3(Tz / 64, Bz * NHz), 256, attn_smem>>>(qkv, att);
    // 3) Output projection: [8192,768] @ [768,768]
    sgemm_bias<<<dim3(Cz / 128, Mz / 128), 256>>>(att, W_proj, b_proj, out,
                                                  Mz, Cz, Cz);
}

// round 5
// speedup vs baseline: 2.5352x; 1.6023x over previous
#include <cuda_runtime.h>
#include <cuda_bf16.h>
#include <cstdint>

// Problem constants
#define Bz 8
#define Tz 1024
#define Cz 768
#define NHz 12
#define HDz 64
#define Mz (Bz * Tz)          // 8192
#define N_QKV (3 * Cz)        // 2304

// Scratch in device globals (no allocations allowed)
__device__ float g_qkv[(size_t)Mz * N_QKV];
__device__ float g_att[(size_t)Mz * Cz];
__device__ __nv_bfloat16 g_xh[(size_t)Mz * Cz],  g_xl[(size_t)Mz * Cz];
__device__ __nv_bfloat16 g_ath[(size_t)Mz * Cz], g_atl[(size_t)Mz * Cz];
__device__ __nv_bfloat16 g_wah[(size_t)N_QKV * Cz], g_wal[(size_t)N_QKV * Cz];
__device__ __nv_bfloat16 g_wph[(size_t)Cz * Cz],  g_wpl[(size_t)Cz * Cz];

// ---------------------------------------------------------------------------
// Base-ISA helpers (sm_80-era PTX: valid on sm_100 base target)
// ---------------------------------------------------------------------------
__device__ __forceinline__ uint32_t smem_u32(const void* p) {
    uint32_t a;
    asm("{ .reg .u64 t; cvta.to.shared.u64 t, %1; cvt.u32.u64 %0, t; }"
        : "=r"(a) : "l"(p));
    return a;
}
__device__ __forceinline__ void cpa16(uint32_t s, const void* g) {
    asm volatile("cp.async.cg.shared.global [%0], [%1], 16;" :: "r"(s), "l"(g));
}
#define CPCOMMIT() asm volatile("cp.async.commit_group;" ::: "memory")
template <int N> __device__ __forceinline__ void cpwait() {
    asm volatile("cp.async.wait_group %0;" :: "n"(N) : "memory");
}
__device__ __forceinline__ void ldsm4(uint32_t* r, uint32_t addr) {
    asm volatile("ldmatrix.sync.aligned.m8n8.x4.shared.b16 {%0,%1,%2,%3}, [%4];"
                 : "=r"(r[0]), "=r"(r[1]), "=r"(r[2]), "=r"(r[3]) : "r"(addr));
}
__device__ __forceinline__ void mma_bf16(float* d, const uint32_t* a,
                                         uint32_t b0, uint32_t b1) {
    asm volatile(
        "mma.sync.aligned.m16n8k16.row.col.f32.bf16.bf16.f32 "
        "{%0,%1,%2,%3}, {%4,%5,%6,%7}, {%8,%9}, {%0,%1,%2,%3};"
        : "+f"(d[0]), "+f"(d[1]), "+f"(d[2]), "+f"(d[3])
        : "r"(a[0]), "r"(a[1]), "r"(a[2]), "r"(a[3]), "r"(b0), "r"(b1));
}

// ---------------------------------------------------------------------------
// Prep kernels: fp32 -> split bf16 (hi + lo)
// ---------------------------------------------------------------------------
__device__ __forceinline__ void split_bf16(float v, __nv_bfloat16& h, __nv_bfloat16& l) {
    h = __float2bfloat16(v);
    l = __float2bfloat16(v - __bfloat162float(h));
}

__global__ __launch_bounds__(256)
void split_kernel(const float* __restrict__ in, __nv_bfloat16* __restrict__ oh,
                  __nv_bfloat16* __restrict__ ol, int n4) {
    int i = blockIdx.x * 256 + threadIdx.x;
    if (i >= n4) return;
    float4 v = *(const float4*)(in + (size_t)i * 4);
    __nv_bfloat16 h[4], l[4];
    split_bf16(v.x, h[0], l[0]);
    split_bf16(v.y, h[1], l[1]);
    split_bf16(v.z, h[2], l[2]);
    split_bf16(v.w, h[3], l[3]);
    *(uint2*)(oh + (size_t)i * 4) = *(uint2*)h;
    *(uint2*)(ol + (size_t)i * 4) = *(uint2*)l;
}

// W [K,N] fp32 -> transposed split bf16 [N,K]
__global__ void tsplit_kernel(const float* __restrict__ W,
                              __nv_bfloat16* __restrict__ oh,
                              __nv_bfloat16* __restrict__ ol, int K, int N) {
    __shared__ float t[32][33];
    int n0 = blockIdx.x * 32, k0 = blockIdx.y * 32;
    int tx = threadIdx.x, ty = threadIdx.y;
#pragma unroll
    for (int r = 0; r < 32; r += 8)
        t[ty + r][tx] = W[(size_t)(k0 + ty + r) * N + n0 + tx];
    __syncthreads();
#pragma unroll
    for (int r = 0; r < 32; r += 8) {
        float v = t[tx][ty + r];
        __nv_bfloat16 h, l;
        split_bf16(v, h, l);
        size_t o = (size_t)(n0 + ty + r) * K + k0 + tx;
        oh[o] = h;
        ol[o] = l;
    }
}

// ---------------------------------------------------------------------------
// mma.sync split-bf16 GEMM: C[M,N] = A[M,K] @ B^T + bias  (B stored [N,K])
// 128x128 CTA tile, BK=32, double-buffered cp.async smem, 8 warps, each warp
// a 64x32 tile of m16n8k16 frags. 3 split-term MMAs (AhBh + AhBl + AlBh).
// Smem rows are 32 bf16 = 64B; swizzle c16 ^= (row>>1)&3 -> ldmatrix
// conflict-free.
// ---------------------------------------------------------------------------
#define STAGE_B 32768
#define OFF_AH 0
#define OFF_AL 8192
#define OFF_BH 16384
#define OFF_BL 24576
#define GEMM_SMEM (2 * STAGE_B)

__device__ __forceinline__ uint32_t sw64(int row, int c16) {
    return (uint32_t)(row * 64 + ((c16 ^ ((row >> 1) & 3)) * 16));
}

__global__ __launch_bounds__(256)
void tc_gemm(const __nv_bfloat16* __restrict__ Ah, const __nv_bfloat16* __restrict__ Al,
             const __nv_bfloat16* __restrict__ Bh, const __nv_bfloat16* __restrict__ Bl,
             const float* __restrict__ bias, float* __restrict__ C, int N, int K) {
    extern __shared__ char smp[];
    const uint32_t sb = smem_u32(smp);

    const int tid = threadIdx.x;
    const int wid = tid >> 5;
    const int lane = tid & 31;
    const int wm = wid & 1;        // 0..1 -> 64-row half
    const int wn = wid >> 1;       // 0..3 -> 32-col quarter
    const int bm = blockIdx.y * 128;
    const int bn = blockIdx.x * 128;
    const int NKC = K >> 5;        // 32-elem K chunks

    // gmem load mapping (per 256-thread pass; 2 passes cover 128x4 16B segs)
    const int lrow0 = tid >> 2;            // 0..63
    const int lc16 = tid & 3;              // 0..3

    // ldmatrix addressing
    const int rowA = wm * 64 + (lane & 15);
    const int rowB = wn * 32 + (lane & 15);
    const int rswA = (rowA >> 1) & 3;
    const int rswB = (rowB >> 1) & 3;
    const int chalf = lane >> 4;           // 0/1

    float acc[4][4][4];
#pragma unroll
    for (int i = 0; i < 4; i++)
#pragma unroll
        for (int j = 0; j < 4; j++)
#pragma unroll
            for (int e = 0; e < 4; e++) acc[i][j][e] = 0.0f;

    // ---- async tile loader ----
    auto load_stage = [&](int kc) {
        const uint32_t stg = sb + (uint32_t)(kc & 1) * STAGE_B;
        const int ke = kc * 32;
#pragma unroll
        for (int v = 0; v < 2; v++) {
            int row = lrow0 + v * 64;
            uint32_t swo = sw64(row, lc16);
            size_t ga = (size_t)(bm + row) * K + ke + lc16 * 8;
            size_t gb = (size_t)(bn + row) * K + ke + lc16 * 8;
            cpa16(stg + OFF_AH + swo, Ah + ga);
            cpa16(stg + OFF_AL + swo, Al + ga);
            cpa16(stg + OFF_BH + swo, Bh + gb);
            cpa16(stg + OFF_BL + swo, Bl + gb);
        }
    };

    load_stage(0);
    CPCOMMIT();

    for (int kc = 0; kc < NKC; kc++) {
        if (kc + 1 < NKC) {
            load_stage(kc + 1);
            CPCOMMIT();
            cpwait<1>();
        } else {
            cpwait<0>();
        }
        __syncthreads();

        const uint32_t stg = sb + (uint32_t)(kc & 1) * STAGE_B;
#pragma unroll
        for (int s16 = 0; s16 < 2; s16++) {
            const int c16 = s16 * 2 + chalf;
            const uint32_t aswc = (uint32_t)((c16 ^ rswA) * 16);
            const uint32_t bswc = (uint32_t)((c16 ^ rswB) * 16);

            uint32_t ah[4][4], al[4][4], bh[2][4], bl[2][4];
#pragma unroll
            for (int i = 0; i < 4; i++) {
                uint32_t ro = (uint32_t)((rowA + 16 * i) * 64);
                ldsm4(ah[i], stg + OFF_AH + ro + aswc);
                ldsm4(al[i], stg + OFF_AL + ro + aswc);
            }
#pragma unroll
            for (int g = 0; g < 2; g++) {
                uint32_t ro = (uint32_t)((rowB + 16 * g) * 64);
                ldsm4(bh[g], stg + OFF_BH + ro + bswc);
                ldsm4(bl[g], stg + OFF_BL + ro + bswc);
            }

#pragma unroll
            for (int i = 0; i < 4; i++)
#pragma unroll
                for (int g = 0; g < 2; g++)
#pragma unroll
                    for (int h = 0; h < 2; h++) {
                        float* d = acc[i][g * 2 + h];
                        mma_bf16(d, ah[i], bh[g][h], bh[g][h + 2]);
                        mma_bf16(d, ah[i], bl[g][h], bl[g][h + 2]);
                        mma_bf16(d, al[i], bh[g][h], bh[g][h + 2]);
                    }
        }
        __syncthreads();
    }

    // ---- epilogue ----
    const int lane4 = lane >> 2;
    const int lm2 = (lane & 3) * 2;
#pragma unroll
    for (int i = 0; i < 4; i++) {
        int r0 = bm + wm * 64 + i * 16 + lane4;
#pragma unroll
        for (int j = 0; j < 4; j++) {
            int cc = bn + wn * 32 + j * 8 + lm2;
            float b0 = bias[cc], b1 = bias[cc + 1];
            float2 v0 = {acc[i][j][0] + b0, acc[i][j][1] + b1};
            float2 v1 = {acc[i][j][2] + b0, acc[i][j][3] + b1};
            *(float2*)&C[(size_t)r0 * N + cc] = v0;
            *(float2*)&C[(size_t)(r0 + 8) * N + cc] = v1;
        }
    }
}

// ---------------------------------------------------------------------------
// Causal flash attention (unchanged from R3, verified)
// ---------------------------------------------------------------------------
__device__ __forceinline__ int sw4(int row, int c4f) {
    return row * 64 + (((c4f) ^ (row >> 2)) & 15) * 4;
}
__device__ __forceinline__ float dot4(float4 a, float4 b) {
    return a.x * b.x + a.y * b.y + a.z * b.z + a.w * b.w;
}

__global__ __launch_bounds__(256)
void attn_kernel(const float* __restrict__ qkv, float* __restrict__ y) {
    extern __shared__ float sm[];
    float* Qs = sm;
    float* Ks = Qs + 64 * 64;
    float* Vs = Ks + 64 * 64;
    float* Ps = Vs + 64 * 64;

    const int tid = threadIdx.x;
    const int bh = blockIdx.y;
    const int b = bh / NHz;
    const int h = bh % NHz;
    const int q0 = blockIdx.x * 64;

    const float* qbase = qkv + (size_t)b * Tz * N_QKV + h * HDz;

    const int ty = tid >> 4;
    const int tx = tid & 15;
    const int ty4 = ty * 4;
    const int tx4 = tx * 4;

#pragma unroll
    for (int t = 0; t < 4; t++) {
        int idx = tid + t * 256;
        int rr = idx >> 4;
        int c4f = idx & 15;
        float4 v = *(const float4*)(qbase + (size_t)(q0 + rr) * N_QKV + c4f * 4);
        v.x *= 0.125f; v.y *= 0.125f; v.z *= 0.125f; v.w *= 0.125f;
        *(float4*)&Qs[sw4(rr, c4f)] = v;
    }

    float m[4], l[4];
    float acc[4][4];
#pragma unroll
    for (int i = 0; i < 4; i++) {
        m[i] = -1e30f; l[i] = 0.0f;
#pragma unroll
        for (int j = 0; j < 4; j++) acc[i][j] = 0.0f;
    }

    const int ntiles = blockIdx.x + 1;
    for (int kt = 0; kt < ntiles; kt++) {
        const int k0 = kt * 64;
        __syncthreads();
#pragma unroll
        for (int t = 0; t < 4; t++) {
            int idx = tid + t * 256;
            int rr = idx >> 4;
            int c4f = idx & 15;
            const float* kb = qbase + (size_t)(k0 + rr) * N_QKV + c4f * 4;
            *(float4*)&Ks[sw4(rr, c4f)] = *(const float4*)(kb + Cz);
            *(float4*)&Vs[sw4(rr, c4f)] = *(const float4*)(kb + 2 * Cz);
        }
        __syncthreads();

        float s[4][4];
#pragma unroll
        for (int i = 0; i < 4; i++)
#pragma unroll
            for (int j = 0; j < 4; j++) s[i][j] = 0.0f;

#pragma unroll 4
        for (int k4f = 0; k4f < 16; k4f++) {
            float4 qf[4], kf[4];
#pragma unroll
            for (int i = 0; i < 4; i++)
                qf[i] = *(const float4*)&Qs[sw4(ty4 + i, k4f)];
#pragma unroll
            for (int j = 0; j < 4; j++)
                kf[j] = *(const float4*)&Ks[sw4(tx4 + j, k4f)];
#pragma unroll
            for (int i = 0; i < 4; i++)
#pragma unroll
                for (int j = 0; j < 4; j++) s[i][j] += dot4(qf[i], kf[j]);
        }

        if (kt == ntiles - 1) {
#pragma unroll
            for (int i = 0; i < 4; i++) {
                int q_idx = q0 + ty4 + i;
#pragma unroll
                for (int j = 0; j < 4; j++) {
                    if (k0 + tx4 + j > q_idx) s[i][j] = -1e30f;
                }
            }
        }

#pragma unroll
        for (int i = 0; i < 4; i++) {
            float mt = fmaxf(fmaxf(s[i][0], s[i][1]), fmaxf(s[i][2], s[i][3]));
            mt = fmaxf(mt, __shfl_xor_sync(0xffffffffu, mt, 1));
            mt = fmaxf(mt, __shfl_xor_sync(0xffffffffu, mt, 2));
            mt = fmaxf(mt, __shfl_xor_sync(0xffffffffu, mt, 4));
            mt = fmaxf(mt, __shfl_xor_sync(0xffffffffu, mt, 8));
            float mnew = fmaxf(m[i], mt);
            float alpha = __expf(m[i] - mnew);

            float4 p;
            p.x = __expf(s[i][0] - mnew);
            p.y = __expf(s[i][1] - mnew);
            p.z = __expf(s[i][2] - mnew);
            p.w = __expf(s[i][3] - mnew);
            float ls = p.x + p.y + p.z + p.w;
            ls += __shfl_xor_sync(0xffffffffu, ls, 1);
            ls += __shfl_xor_sync(0xffffffffu, ls, 2);
            ls += __shfl_xor_sync(0xffffffffu, ls, 4);
            ls += __shfl_xor_sync(0xffffffffu, ls, 8);

            *(float4*)&Ps[sw4(ty4 + i, tx)] = p;
            l[i] = l[i] * alpha + ls;
            m[i] = mnew;
#pragma unroll
            for (int j = 0; j < 4; j++) acc[i][j] *= alpha;
        }
        __syncthreads();

#pragma unroll 4
        for (int k4f = 0; k4f < 16; k4f++) {
            float4 pf[4], vf[4];
#pragma unroll
            for (int i = 0; i < 4; i++)
                pf[i] = *(const float4*)&Ps[sw4(ty4 + i, k4f)];
#pragma unroll
            for (int kk = 0; kk < 4; kk++)
                vf[kk] = *(const float4*)&Vs[sw4(k4f * 4 + kk, tx)];
#pragma unroll
            for (int i = 0; i < 4; i++) {
                acc[i][0] += pf[i].x * vf[0].x + pf[i].y * vf[1].x
                           + pf[i].z * vf[2].x + pf[i].w * vf[3].x;
                acc[i][1] += pf[i].x * vf[0].y + pf[i].y * vf[1].y
                           + pf[i].z * vf[2].y + pf[i].w * vf[3].y;
                acc[i][2] += pf[i].x * vf[0].z + pf[i].y * vf[1].z
                           + pf[i].z * vf[2].z + pf[i].w * vf[3].z;
                acc[i][3] += pf[i].x * vf[0].w + pf[i].y * vf[1].w
                           + pf[i].z * vf[2].w + pf[i].w * vf[3].w;
            }
        }
    }

#pragma unroll
    for (int i = 0; i < 4; i++) {
        float inv = 1.0f / l[i];
        float4 o;
        o.x = acc[i][0] * inv;
        o.y = acc[i][1] * inv;
        o.z = acc[i][2] * inv;
        o.w = acc[i][3] * inv;
        float* yb = y + (size_t)(b * Tz + q0 + ty4 + i) * Cz + h * HDz + tx4;
        *(float4*)yb = o;
    }
}

// ---------------------------------------------------------------------------
// Launch
// ---------------------------------------------------------------------------
extern "C" void kernel_launch(void* const* d_in, const int* in_sizes, int n_in,
                              void* d_out, int out_size) {
    const float* x      = (const float*)d_in[0];
    const float* W_attn = (const float*)d_in[1];
    const float* b_attn = (const float*)d_in[2];
    const float* W_proj = (const float*)d_in[3];
    const float* b_proj = (const float*)d_in[4];
    float* out = (float*)d_out;

    float *qkv, *att;
    __nv_bfloat16 *xh, *xl, *ath, *atl, *wah, *wal, *wph, *wpl;
    cudaGetSymbolAddress((void**)&qkv, g_qkv);
    cudaGetSymbolAddress((void**)&att, g_att);
    cudaGetSymbolAddress((void**)&xh, g_xh);
    cudaGetSymbolAddress((void**)&xl, g_xl);
    cudaGetSymbolAddress((void**)&ath, g_ath);
    cudaGetSymbolAddress((void**)&atl, g_atl);
    cudaGetSymbolAddress((void**)&wah, g_wah);
    cudaGetSymbolAddress((void**)&wal, g_wal);
    cudaGetSymbolAddress((void**)&wph, g_wph);
    cudaGetSymbolAddress((void**)&wpl, g_wpl);

    cudaFuncSetAttribute(tc_gemm, cudaFuncAttributeMaxDynamicSharedMemorySize, GEMM_SMEM);
    const int attn_smem = 4 * 64 * 64 * (int)sizeof(float);
    cudaFuncSetAttribute(attn_kernel, cudaFuncAttributeMaxDynamicSharedMemorySize, attn_smem);

    const int n4 = Mz * Cz / 4;

    // Prep: split x, transpose-split weights
    split_kernel<<<n4 / 256, 256>>>(x, xh, xl, n4);
    tsplit_kernel<<<dim3(N_QKV / 32, Cz / 32), dim3(32, 8)>>>(W_attn, wah, wal, Cz, N_QKV);
    tsplit_kernel<<<dim3(Cz / 32, Cz / 32), dim3(32, 8)>>>(W_proj, wph, wpl, Cz, Cz);

    // 1) QKV projection on tensor cores
    tc_gemm<<<dim3(N_QKV / 128, Mz / 128), 256, GEMM_SMEM>>>(xh, xl, wah, wal,
                                                             b_attn, qkv, N_QKV, Cz);
    // 2) Causal attention (fp32)
    attn_kernel<<<dim3(Tz / 64, Bz * NHz), 256, attn_smem>>>(qkv, att);

    // 3) Output projection on tensor cores
    split_kernel<<<n4 / 256, 256>>>(att, ath, atl, n4);
    tc_gemm<<<dim3(Cz / 128, Mz / 128), 256, GEMM_SMEM>>>(ath, atl, wph, wpl,
                                                          b_proj, out, Cz, Cz);
}

// round 6
// speedup vs baseline: 3.9962x; 1.5763x over previous
#include <cuda_runtime.h>
#include <cuda_bf16.h>
#include <cstdint>

// Problem constants
#define Bz 8
#define Tz 1024
#define Cz 768
#define NHz 12
#define HDz 64
#define Mz (Bz * Tz)          // 8192
#define N_QKV (3 * Cz)        // 2304

// Scratch in device globals (no allocations allowed)
__device__ __nv_bfloat16 g_xh[(size_t)Mz * Cz],  g_xl[(size_t)Mz * Cz];
__device__ __nv_bfloat16 g_qkvh[(size_t)Mz * N_QKV], g_qkvl[(size_t)Mz * N_QKV];
__device__ __nv_bfloat16 g_ath[(size_t)Mz * Cz], g_atl[(size_t)Mz * Cz];
__device__ __nv_bfloat16 g_wah[(size_t)N_QKV * Cz], g_wal[(size_t)N_QKV * Cz];
__device__ __nv_bfloat16 g_wph[(size_t)Cz * Cz],  g_wpl[(size_t)Cz * Cz];

// ---------------------------------------------------------------------------
// Base-ISA helpers
// ---------------------------------------------------------------------------
__device__ __forceinline__ uint32_t smem_u32(const void* p) {
    uint32_t a;
    asm("{ .reg .u64 t; cvta.to.shared.u64 t, %1; cvt.u32.u64 %0, t; }"
        : "=r"(a) : "l"(p));
    return a;
}
__device__ __forceinline__ void cpa16(uint32_t s, const void* g) {
    asm volatile("cp.async.cg.shared.global [%0], [%1], 16;" :: "r"(s), "l"(g));
}
#define CPCOMMIT() asm volatile("cp.async.commit_group;" ::: "memory")
template <int N> __device__ __forceinline__ void cpwait() {
    asm volatile("cp.async.wait_group %0;" :: "n"(N) : "memory");
}
__device__ __forceinline__ void ldsm4(uint32_t* r, uint32_t addr) {
    asm volatile("ldmatrix.sync.aligned.m8n8.x4.shared.b16 {%0,%1,%2,%3}, [%4];"
                 : "=r"(r[0]), "=r"(r[1]), "=r"(r[2]), "=r"(r[3]) : "r"(addr));
}
__device__ __forceinline__ void ldsm4t(uint32_t* r, uint32_t addr) {
    asm volatile("ldmatrix.sync.aligned.m8n8.x4.trans.shared.b16 {%0,%1,%2,%3}, [%4];"
                 : "=r"(r[0]), "=r"(r[1]), "=r"(r[2]), "=r"(r[3]) : "r"(addr));
}
__device__ __forceinline__ void mma_bf16(float* d, const uint32_t* a,
                                         uint32_t b0, uint32_t b1) {
    asm volatile(
        "mma.sync.aligned.m16n8k16.row.col.f32.bf16.bf16.f32 "
        "{%0,%1,%2,%3}, {%4,%5,%6,%7}, {%8,%9}, {%0,%1,%2,%3};"
        : "+f"(d[0]), "+f"(d[1]), "+f"(d[2]), "+f"(d[3])
        : "r"(a[0]), "r"(a[1]), "r"(a[2]), "r"(a[3]), "r"(b0), "r"(b1));
}
__device__ __forceinline__ void split_bf16(float v, __nv_bfloat16& h, __nv_bfloat16& l) {
    h = __float2bfloat16(v);
    l = __float2bfloat16(v - __bfloat162float(h));
}
__device__ __forceinline__ uint32_t pack_bf16(float a, float b) {
    __nv_bfloat162 t;
    t.x = __float2bfloat16(a);
    t.y = __float2bfloat16(b);
    return *(uint32_t*)&t;
}

// ---------------------------------------------------------------------------
// Prep kernels
// ---------------------------------------------------------------------------
__global__ __launch_bounds__(256)
void split_kernel(const float* __restrict__ in, __nv_bfloat16* __restrict__ oh,
                  __nv_bfloat16* __restrict__ ol, int n4) {
    int i = blockIdx.x * 256 + threadIdx.x;
    if (i >= n4) return;
    float4 v = *(const float4*)(in + (size_t)i * 4);
    __nv_bfloat16 h[4], l[4];
    split_bf16(v.x, h[0], l[0]);
    split_bf16(v.y, h[1], l[1]);
    split_bf16(v.z, h[2], l[2]);
    split_bf16(v.w, h[3], l[3]);
    *(uint2*)(oh + (size_t)i * 4) = *(uint2*)h;
    *(uint2*)(ol + (size_t)i * 4) = *(uint2*)l;
}

__global__ void tsplit_kernel(const float* __restrict__ W,
                              __nv_bfloat16* __restrict__ oh,
                              __nv_bfloat16* __restrict__ ol, int K, int N) {
    __shared__ float t[32][33];
    int n0 = blockIdx.x * 32, k0 = blockIdx.y * 32;
    int tx = threadIdx.x, ty = threadIdx.y;
#pragma unroll
    for (int r = 0; r < 32; r += 8)
        t[ty + r][tx] = W[(size_t)(k0 + ty + r) * N + n0 + tx];
    __syncthreads();
#pragma unroll
    for (int r = 0; r < 32; r += 8) {
        float v = t[tx][ty + r];
        __nv_bfloat16 h, l;
        split_bf16(v, h, l);
        size_t o = (size_t)(n0 + ty + r) * K + k0 + tx;
        oh[o] = h;
        ol[o] = l;
    }
}

// ---------------------------------------------------------------------------
// mma.sync split-bf16 GEMM (R5, verified). SPLIT_OUT writes bf16 hi/lo
// instead of fp32.
// ---------------------------------------------------------------------------
#define STAGE_B 32768
#define OFF_AH 0
#define OFF_AL 8192
#define OFF_BH 16384
#define OFF_BL 24576
#define GEMM_SMEM (2 * STAGE_B)

__device__ __forceinline__ uint32_t sw64(int row, int c16) {
    return (uint32_t)(row * 64 + ((c16 ^ ((row >> 1) & 3)) * 16));
}

template <bool SPLIT_OUT>
__global__ __launch_bounds__(256)
void tc_gemm(const __nv_bfloat16* __restrict__ Ah, const __nv_bfloat16* __restrict__ Al,
             const __nv_bfloat16* __restrict__ Bh, const __nv_bfloat16* __restrict__ Bl,
             const float* __restrict__ bias, float* __restrict__ C,
             __nv_bfloat16* __restrict__ Ch, __nv_bfloat16* __restrict__ Cl,
             int N, int K) {
    extern __shared__ char smp[];
    const uint32_t sb = smem_u32(smp);

    const int tid = threadIdx.x;
    const int wid = tid >> 5;
    const int lane = tid & 31;
    const int wm = wid & 1;
    const int wn = wid >> 1;
    const int bm = blockIdx.y * 128;
    const int bn = blockIdx.x * 128;
    const int NKC = K >> 5;

    const int lrow0 = tid >> 2;
    const int lc16 = tid & 3;

    const int rowA = wm * 64 + (lane & 15);
    const int rowB = wn * 32 + (lane & 15);
    const int rswA = (rowA >> 1) & 3;
    const int rswB = (rowB >> 1) & 3;
    const int chalf = lane >> 4;

    float acc[4][4][4];
#pragma unroll
    for (int i = 0; i < 4; i++)
#pragma unroll
        for (int j = 0; j < 4; j++)
#pragma unroll
            for (int e = 0; e < 4; e++) acc[i][j][e] = 0.0f;

    auto load_stage = [&](int kc) {
        const uint32_t stg = sb + (uint32_t)(kc & 1) * STAGE_B;
        const int ke = kc * 32;
#pragma unroll
        for (int v = 0; v < 2; v++) {
            int row = lrow0 + v * 64;
            uint32_t swo = sw64(row, lc16);
            size_t ga = (size_t)(bm + row) * K + ke + lc16 * 8;
            size_t gb = (size_t)(bn + row) * K + ke + lc16 * 8;
            cpa16(stg + OFF_AH + swo, Ah + ga);
            cpa16(stg + OFF_AL + swo, Al + ga);
            cpa16(stg + OFF_BH + swo, Bh + gb);
            cpa16(stg + OFF_BL + swo, Bl + gb);
        }
    };

    load_stage(0);
    CPCOMMIT();

    for (int kc = 0; kc < NKC; kc++) {
        if (kc + 1 < NKC) {
            load_stage(kc + 1);
            CPCOMMIT();
            cpwait<1>();
        } else {
            cpwait<0>();
        }
        __syncthreads();

        const uint32_t stg = sb + (uint32_t)(kc & 1) * STAGE_B;
#pragma unroll
        for (int s16 = 0; s16 < 2; s16++) {
            const int c16 = s16 * 2 + chalf;
            const uint32_t aswc = (uint32_t)((c16 ^ rswA) * 16);
            const uint32_t bswc = (uint32_t)((c16 ^ rswB) * 16);

            uint32_t ah[4][4], al[4][4], bh[2][4], bl[2][4];
#pragma unroll
            for (int i = 0; i < 4; i++) {
                uint32_t ro = (uint32_t)((rowA + 16 * i) * 64);
                ldsm4(ah[i], stg + OFF_AH + ro + aswc);
                ldsm4(al[i], stg + OFF_AL + ro + aswc);
            }
#pragma unroll
            for (int g = 0; g < 2; g++) {
                uint32_t ro = (uint32_t)((rowB + 16 * g) * 64);
                ldsm4(bh[g], stg + OFF_BH + ro + bswc);
                ldsm4(bl[g], stg + OFF_BL + ro + bswc);
            }

#pragma unroll
            for (int i = 0; i < 4; i++)
#pragma unroll
                for (int g = 0; g < 2; g++)
#pragma unroll
                    for (int h = 0; h < 2; h++) {
                        float* d = acc[i][g * 2 + h];
                        mma_bf16(d, ah[i], bh[g][h], bh[g][h + 2]);
                        mma_bf16(d, ah[i], bl[g][h], bl[g][h + 2]);
                        mma_bf16(d, al[i], bh[g][h], bh[g][h + 2]);
                    }
        }
        __syncthreads();
    }

    const int lane4 = lane >> 2;
    const int lm2 = (lane & 3) * 2;
#pragma unroll
    for (int i = 0; i < 4; i++) {
        int r0 = bm + wm * 64 + i * 16 + lane4;
#pragma unroll
        for (int j = 0; j < 4; j++) {
            int cc = bn + wn * 32 + j * 8 + lm2;
            float b0 = bias[cc], b1 = bias[cc + 1];
            float v00 = acc[i][j][0] + b0, v01 = acc[i][j][1] + b1;
            float v10 = acc[i][j][2] + b0, v11 = acc[i][j][3] + b1;
            if (SPLIT_OUT) {
                __nv_bfloat16 h0, l0, h1, l1;
                split_bf16(v00, h0, l0);
                split_bf16(v01, h1, l1);
                __nv_bfloat162 ph = {h0, h1}, pl = {l0, l1};
                *(uint32_t*)&Ch[(size_t)r0 * N + cc] = *(uint32_t*)&ph;
                *(uint32_t*)&Cl[(size_t)r0 * N + cc] = *(uint32_t*)&pl;
                split_bf16(v10, h0, l0);
                split_bf16(v11, h1, l1);
                __nv_bfloat162 qh = {h0, h1}, ql = {l0, l1};
                *(uint32_t*)&Ch[(size_t)(r0 + 8) * N + cc] = *(uint32_t*)&qh;
                *(uint32_t*)&Cl[(size_t)(r0 + 8) * N + cc] = *(uint32_t*)&ql;
            } else {
                *(float2*)&C[(size_t)r0 * N + cc] = {v00, v01};
                *(float2*)&C[(size_t)(r0 + 8) * N + cc] = {v10, v11};
            }
        }
    }
}

// ---------------------------------------------------------------------------
// Tensor-core causal flash attention.
// CTA: 128 q-rows x one (b,h). 8 warps x 16 q-rows. KV tiles of 64,
// double-buffered cp.async. Split-bf16 3-term for both S and PV.
// Smem rows: 64 bf16 = 128B, swizzle c16 ^= (row & 7).
// ---------------------------------------------------------------------------
#define AOFF_QH 0
#define AOFF_QL 16384
#define AOFF_KV 32768
#define ASTG 32768
#define AOFF_KH 0
#define AOFF_KL 8192
#define AOFF_VH 16384
#define AOFF_VL 24576
#define ATT_SMEM (AOFF_KV + 2 * ASTG)   // 98304

__device__ __forceinline__ uint32_t asw(int row, int c16) {
    return (uint32_t)(row * 128 + ((c16 ^ (row & 7)) * 16));
}

__global__ __launch_bounds__(256)
void attn_tc(const __nv_bfloat16* __restrict__ qh,
             const __nv_bfloat16* __restrict__ ql,
             __nv_bfloat16* __restrict__ oh, __nv_bfloat16* __restrict__ ol) {
    extern __shared__ char smp[];
    const uint32_t sb = smem_u32(smp);

    const int tid = threadIdx.x;
    const int wid = tid >> 5;
    const int lane = tid & 31;
    const int bh = blockIdx.y;
    const int b = bh / NHz;
    const int h = bh % NHz;
    const int q0 = blockIdx.x * 128;

    const __nv_bfloat16* qbh = qh + (size_t)b * Tz * N_QKV + h * HDz;
    const __nv_bfloat16* qbl = ql + (size_t)b * Tz * N_QKV + h * HDz;

    // ---- load Q tile (hi+lo) ----
#pragma unroll
    for (int i = 0; i < 4; i++) {
        int idx = tid + i * 256;
        int row = idx >> 3;
        int c = idx & 7;
        uint32_t swo = asw(row, c);
        size_t g = (size_t)(q0 + row) * N_QKV + c * 8;
        cpa16(sb + AOFF_QH + swo, qbh + g);
        cpa16(sb + AOFF_QL + swo, qbl + g);
    }
    CPCOMMIT();

    auto load_kv = [&](int kt) {
        const uint32_t stg = sb + AOFF_KV + (uint32_t)(kt & 1) * ASTG;
        const int k0 = kt * 64;
#pragma unroll
        for (int v = 0; v < 2; v++) {
            int row = (tid >> 3) + v * 32;
            int c = tid & 7;
            uint32_t swo = asw(row, c);
            size_t g = (size_t)(k0 + row) * N_QKV + c * 8;
            cpa16(stg + AOFF_KH + swo, qbh + g + Cz);
            cpa16(stg + AOFF_KL + swo, qbl + g + Cz);
            cpa16(stg + AOFF_VH + swo, qbh + g + 2 * Cz);
            cpa16(stg + AOFF_VL + swo, qbl + g + 2 * Cz);
        }
    };

    load_kv(0);
    CPCOMMIT();
    cpwait<1>();        // Q arrived
    __syncthreads();

    // ---- hoist Q fragments (persist across all KV tiles) ----
    const int rowQ = wid * 16 + (lane & 15);
    const int chalf = lane >> 4;
    uint32_t qfh[4][4], qfl[4][4];
#pragma unroll
    for (int kc = 0; kc < 4; kc++) {
        int c16 = kc * 2 + chalf;
        uint32_t ad = (uint32_t)(rowQ * 128 + ((c16 ^ (rowQ & 7)) * 16));
        ldsm4(qfh[kc], sb + AOFF_QH + ad);
        ldsm4(qfl[kc], sb + AOFF_QL + ad);
    }

    const int grp = lane >> 2;          // row-in-16 (lo); hi = +8
    const int lm2 = (lane & 3) * 2;

    float oacc[8][4];
#pragma unroll
    for (int nf = 0; nf < 8; nf++)
#pragma unroll
        for (int e = 0; e < 4; e++) oacc[nf][e] = 0.0f;
    float mrow[2] = {-1e30f, -1e30f};
    float lrow[2] = {0.0f, 0.0f};

    const int ntiles = (q0 + 128) / 64;
    for (int kt = 0; kt < ntiles; kt++) {
        if (kt + 1 < ntiles) {
            load_kv(kt + 1);
            CPCOMMIT();
            cpwait<1>();
        } else {
            cpwait<0>();
        }
        __syncthreads();

        const uint32_t stg = sb + AOFF_KV + (uint32_t)(kt & 1) * ASTG;
        const int k0 = kt * 64;

        // ---- S = Q K^T (3-term) ----
        float sacc[8][4];
#pragma unroll
        for (int nf = 0; nf < 8; nf++)
#pragma unroll
            for (int e = 0; e < 4; e++) sacc[nf][e] = 0.0f;

#pragma unroll
        for (int kc = 0; kc < 4; kc++) {
            int c16 = kc * 2 + chalf;
            uint32_t kh[4][4], kl[4][4];
#pragma unroll
            for (int g = 0; g < 4; g++) {
                int rowK = g * 16 + (lane & 15);
                uint32_t ad = (uint32_t)(rowK * 128 + ((c16 ^ (rowK & 7)) * 16));
                ldsm4(kh[g], stg + AOFF_KH + ad);
                ldsm4(kl[g], stg + AOFF_KL + ad);
            }
#pragma unroll
            for (int g = 0; g < 4; g++)
#pragma unroll
                for (int hh = 0; hh < 2; hh++) {
                    float* d = sacc[g * 2 + hh];
                    mma_bf16(d, qfh[kc], kh[g][hh], kh[g][hh + 2]);
                    mma_bf16(d, qfh[kc], kl[g][hh], kl[g][hh + 2]);
                    mma_bf16(d, qfl[kc], kh[g][hh], kh[g][hh + 2]);
                }
        }

        // ---- scale + causal mask ----
        const bool domask = (k0 + 63 > q0);
#pragma unroll
        for (int nf = 0; nf < 8; nf++)
#pragma unroll
            for (int e = 0; e < 4; e++) {
                float s = sacc[nf][e] * 0.125f;
                if (domask) {
                    int kcol = k0 + nf * 8 + lm2 + (e & 1);
                    int qrow = q0 + wid * 16 + grp + ((e >> 1) << 3);
                    if (kcol > qrow) s = -1e30f;
                }
                sacc[nf][e] = s;
            }

        // ---- online softmax (2 rows per thread, quad reduction) ----
#pragma unroll
        for (int r = 0; r < 2; r++) {
            float mt = -1e30f;
#pragma unroll
            for (int nf = 0; nf < 8; nf++)
                mt = fmaxf(mt, fmaxf(sacc[nf][2 * r], sacc[nf][2 * r + 1]));
            mt = fmaxf(mt, __shfl_xor_sync(0xffffffffu, mt, 1));
            mt = fmaxf(mt, __shfl_xor_sync(0xffffffffu, mt, 2));
            float mnew = fmaxf(mrow[r], mt);
            float alpha = __expf(mrow[r] - mnew);
            float ls = 0.0f;
#pragma unroll
            for (int nf = 0; nf < 8; nf++) {
                float p0 = __expf(sacc[nf][2 * r] - mnew);
                float p1 = __expf(sacc[nf][2 * r + 1] - mnew);
                sacc[nf][2 * r] = p0;
                sacc[nf][2 * r + 1] = p1;
                ls += p0 + p1;
            }
            ls += __shfl_xor_sync(0xffffffffu, ls, 1);
            ls += __shfl_xor_sync(0xffffffffu, ls, 2);
            lrow[r] = lrow[r] * alpha + ls;
            mrow[r] = mnew;
#pragma unroll
            for (int nf = 0; nf < 8; nf++) {
                oacc[nf][2 * r] *= alpha;
                oacc[nf][2 * r + 1] *= alpha;
            }
        }

        // ---- P -> split bf16 A-fragments (in-register) ----
        uint32_t pfh[4][4], pfl[4][4];
#pragma unroll
        for (int kc = 0; kc < 4; kc++) {
#pragma unroll
            for (int part = 0; part < 4; part++) {
                int nf = kc * 2 + (part >> 1);
                int e = (part & 1) * 2;
                float p0 = sacc[nf][e], p1 = sacc[nf][e + 1];
                __nv_bfloat16 h0, l0, h1, l1;
                split_bf16(p0, h0, l0);
                split_bf16(p1, h1, l1);
                __nv_bfloat162 vh2 = {h0, h1}, vl2 = {l0, l1};
                pfh[kc][part] = *(uint32_t*)&vh2;
                pfl[kc][part] = *(uint32_t*)&vl2;
            }
        }
        // reorder: A frag = {a0 rows lo k0-7, a1 rows hi k0-7, a2 rows lo k8-15, a3 rows hi k8-15}
        // built above as part: 0 = nf even e0 (rows lo), 1 = nf even e2?? fix mapping:
        //   part0: nf=2kc, e=0/1 -> rows lo cols k0-7  => a0
        //   part1: nf=2kc, e=2/3 -> rows hi cols k0-7  => a1
        //   part2: nf=2kc+1, e=0/1 -> rows lo k8-15    => a2
        //   part3: nf=2kc+1, e=2/3 -> rows hi k8-15    => a3
        // (matches A-frag order already)

        // ---- O += P V (3-term), V via ldmatrix.trans ----
#pragma unroll
        for (int kc = 0; kc < 4; kc++) {
#pragma unroll
            for (int vg = 0; vg < 2; vg++) {
                // two x4t loads cover d = vg*32 .. vg*32+31
#pragma unroll
                for (int half = 0; half < 2; half++) {
                    int rowV = kc * 16 + (lane & 7) + ((lane >> 3) & 1) * 8;
                    int c16 = vg * 4 + half * 2 + (lane >> 4);
                    uint32_t ad = (uint32_t)(rowV * 128 + ((c16 ^ (rowV & 7)) * 16));
                    uint32_t vh[4], vl[4];
                    ldsm4t(vh, stg + AOFF_VH + ad);
                    ldsm4t(vl, stg + AOFF_VL + ad);
                    int nf0 = vg * 4 + half * 2;
                    float* d0 = oacc[nf0];
                    float* d1 = oacc[nf0 + 1];
                    mma_bf16(d0, pfh[kc], vh[0], vh[1]);
                    mma_bf16(d0, pfh[kc], vl[0], vl[1]);
                    mma_bf16(d0, pfl[kc], vh[0], vh[1]);
                    mma_bf16(d1, pfh[kc], vh[2], vh[3]);
                    mma_bf16(d1, pfh[kc], vl[2], vl[3]);
                    mma_bf16(d1, pfl[kc], vh[2], vh[3]);
                }
            }
        }
        __syncthreads();
    }

    // ---- epilogue: normalize, split, store bf16 hi/lo ----
#pragma unroll
    for (int r = 0; r < 2; r++) {
        float inv = 1.0f / lrow[r];
        size_t row = (size_t)(b * Tz + q0 + wid * 16 + grp + r * 8);
#pragma unroll
        for (int nf = 0; nf < 8; nf++) {
            float v0 = oacc[nf][2 * r] * inv;
            float v1 = oacc[nf][2 * r + 1] * inv;
            __nv_bfloat16 h0, l0, h1, l1;
            split_bf16(v0, h0, l0);
            split_bf16(v1, h1, l1);
            __nv_bfloat162 ph = {h0, h1}, pl = {l0, l1};
            size_t o = row * Cz + h * HDz + nf * 8 + lm2;
            *(uint32_t*)&oh[o] = *(uint32_t*)&ph;
            *(uint32_t*)&ol[o] = *(uint32_t*)&pl;
        }
    }
}

// ---------------------------------------------------------------------------
// Launch
// ---------------------------------------------------------------------------
extern "C" void kernel_launch(void* const* d_in, const int* in_sizes, int n_in,
                              void* d_out, int out_size) {
    const float* x      = (const float*)d_in[0];
    const float* W_attn = (const float*)d_in[1];
    const float* b_attn = (const float*)d_in[2];
    const float* W_proj = (const float*)d_in[3];
    const float* b_proj = (const float*)d_in[4];
    float* out = (float*)d_out;

    __nv_bfloat16 *xh, *xl, *qkvh, *qkvl, *ath, *atl, *wah, *wal, *wph, *wpl;
    cudaGetSymbolAddress((void**)&xh, g_xh);
    cudaGetSymbolAddress((void**)&xl, g_xl);
    cudaGetSymbolAddress((void**)&qkvh, g_qkvh);
    cudaGetSymbolAddress((void**)&qkvl, g_qkvl);
    cudaGetSymbolAddress((void**)&ath, g_ath);
    cudaGetSymbolAddress((void**)&atl, g_atl);
    cudaGetSymbolAddress((void**)&wah, g_wah);
    cudaGetSymbolAddress((void**)&wal, g_wal);
    cudaGetSymbolAddress((void**)&wph, g_wph);
    cudaGetSymbolAddress((void**)&wpl, g_wpl);

    cudaFuncSetAttribute(tc_gemm<true>, cudaFuncAttributeMaxDynamicSharedMemorySize, GEMM_SMEM);
    cudaFuncSetAttribute(tc_gemm<false>, cudaFuncAttributeMaxDynamicSharedMemorySize, GEMM_SMEM);
    cudaFuncSetAttribute(attn_tc, cudaFuncAttributeMaxDynamicSharedMemorySize, ATT_SMEM);

    const int n4 = Mz * Cz / 4;

    split_kernel<<<n4 / 256, 256>>>(x, xh, xl, n4);
    tsplit_kernel<<<dim3(N_QKV / 32, Cz / 32), dim3(32, 8)>>>(W_attn, wah, wal, Cz, N_QKV);
    tsplit_kernel<<<dim3(Cz / 32, Cz / 32), dim3(32, 8)>>>(W_proj, wph, wpl, Cz, Cz);

    // 1) QKV projection -> split bf16 output
    tc_gemm<true><<<dim3(N_QKV / 128, Mz / 128), 256, GEMM_SMEM>>>(
        xh, xl, wah, wal, b_attn, nullptr, qkvh, qkvl, N_QKV, Cz);

    // 2) Tensor-core causal attention -> split bf16 output
    attn_tc<<<dim3(Tz / 128, Bz * NHz), 256, ATT_SMEM>>>(qkvh, qkvl, ath, atl);

    // 3) Output projection -> fp32
    tc_gemm<false><<<dim3(Cz / 128, Mz / 128), 256, GEMM_SMEM>>>(
        ath, atl, wph, wpl, b_proj, out, nullptr, nullptr, Cz, Cz);
}

// round 7
// speedup vs baseline: 4.3342x; 1.0846x over previous
#include <cuda_runtime.h>
#include <cuda_bf16.h>
#include <cstdint>

// Problem constants
#define Bz 8
#define Tz 1024
#define Cz 768
#define NHz 12
#define HDz 64
#define Mz (Bz * Tz)          // 8192
#define N_QKV (3 * Cz)        // 2304

// Scratch in device globals (no allocations allowed)
__device__ __nv_bfloat16 g_xh[(size_t)Mz * Cz],  g_xl[(size_t)Mz * Cz];
__device__ __nv_bfloat16 g_qkvh[(size_t)Mz * N_QKV], g_qkvl[(size_t)Mz * N_QKV];
__device__ __nv_bfloat16 g_ath[(size_t)Mz * Cz], g_atl[(size_t)Mz * Cz];
__device__ __nv_bfloat16 g_wah[(size_t)N_QKV * Cz], g_wal[(size_t)N_QKV * Cz];
__device__ __nv_bfloat16 g_wph[(size_t)Cz * Cz],  g_wpl[(size_t)Cz * Cz];

// ---------------------------------------------------------------------------
// Base-ISA helpers
// ---------------------------------------------------------------------------
__device__ __forceinline__ uint32_t smem_u32(const void* p) {
    uint32_t a;
    asm("{ .reg .u64 t; cvta.to.shared.u64 t, %1; cvt.u32.u64 %0, t; }"
        : "=r"(a) : "l"(p));
    return a;
}
__device__ __forceinline__ void cpa16(uint32_t s, const void* g) {
    asm volatile("cp.async.cg.shared.global [%0], [%1], 16;" :: "r"(s), "l"(g));
}
#define CPCOMMIT() asm volatile("cp.async.commit_group;" ::: "memory")
template <int N> __device__ __forceinline__ void cpwait() {
    asm volatile("cp.async.wait_group %0;" :: "n"(N) : "memory");
}
__device__ __forceinline__ void ldsm4(uint32_t* r, uint32_t addr) {
    asm volatile("ldmatrix.sync.aligned.m8n8.x4.shared.b16 {%0,%1,%2,%3}, [%4];"
                 : "=r"(r[0]), "=r"(r[1]), "=r"(r[2]), "=r"(r[3]) : "r"(addr));
}
__device__ __forceinline__ void ldsm4t(uint32_t* r, uint32_t addr) {
    asm volatile("ldmatrix.sync.aligned.m8n8.x4.trans.shared.b16 {%0,%1,%2,%3}, [%4];"
                 : "=r"(r[0]), "=r"(r[1]), "=r"(r[2]), "=r"(r[3]) : "r"(addr));
}
// NOTE: non-volatile — pure register op; lets ptxas pipeline independent MMAs.
__device__ __forceinline__ void mma_bf16(float* d, const uint32_t* a,
                                         uint32_t b0, uint32_t b1) {
    asm("mma.sync.aligned.m16n8k16.row.col.f32.bf16.bf16.f32 "
        "{%0,%1,%2,%3}, {%4,%5,%6,%7}, {%8,%9}, {%0,%1,%2,%3};"
        : "+f"(d[0]), "+f"(d[1]), "+f"(d[2]), "+f"(d[3])
        : "r"(a[0]), "r"(a[1]), "r"(a[2]), "r"(a[3]), "r"(b0), "r"(b1));
}
__device__ __forceinline__ void split_bf16(float v, __nv_bfloat16& h, __nv_bfloat16& l) {
    h = __float2bfloat16(v);
    l = __float2bfloat16(v - __bfloat162float(h));
}

// ---------------------------------------------------------------------------
// Prep kernels
// ---------------------------------------------------------------------------
__global__ __launch_bounds__(256)
void split_kernel(const float* __restrict__ in, __nv_bfloat16* __restrict__ oh,
                  __nv_bfloat16* __restrict__ ol, int n4) {
    int i = blockIdx.x * 256 + threadIdx.x;
    if (i >= n4) return;
    float4 v = *(const float4*)(in + (size_t)i * 4);
    __nv_bfloat16 h[4], l[4];
    split_bf16(v.x, h[0], l[0]);
    split_bf16(v.y, h[1], l[1]);
    split_bf16(v.z, h[2], l[2]);
    split_bf16(v.w, h[3], l[3]);
    *(uint2*)(oh + (size_t)i * 4) = *(uint2*)h;
    *(uint2*)(ol + (size_t)i * 4) = *(uint2*)l;
}

__global__ void tsplit_kernel(const float* __restrict__ W,
                              __nv_bfloat16* __restrict__ oh,
                              __nv_bfloat16* __restrict__ ol, int K, int N) {
    __shared__ float t[32][33];
    int n0 = blockIdx.x * 32, k0 = blockIdx.y * 32;
    int tx = threadIdx.x, ty = threadIdx.y;
#pragma unroll
    for (int r = 0; r < 32; r += 8)
        t[ty + r][tx] = W[(size_t)(k0 + ty + r) * N + n0 + tx];
    __syncthreads();
#pragma unroll
    for (int r = 0; r < 32; r += 8) {
        float v = t[tx][ty + r];
        __nv_bfloat16 h, l;
        split_bf16(v, h, l);
        size_t o = (size_t)(n0 + ty + r) * K + k0 + tx;
        oh[o] = h;
        ol[o] = l;
    }
}

// ---------------------------------------------------------------------------
// mma.sync split-bf16 GEMM. Term-major MMA ordering, single sync per k-iter.
// ---------------------------------------------------------------------------
#define STAGE_B 32768
#define OFF_AH 0
#define OFF_AL 8192
#define OFF_BH 16384
#define OFF_BL 24576
#define GEMM_SMEM (2 * STAGE_B)

__device__ __forceinline__ uint32_t sw64(int row, int c16) {
    return (uint32_t)(row * 64 + ((c16 ^ ((row >> 1) & 3)) * 16));
}

template <bool SPLIT_OUT>
__global__ __launch_bounds__(256)
void tc_gemm(const __nv_bfloat16* __restrict__ Ah, const __nv_bfloat16* __restrict__ Al,
             const __nv_bfloat16* __restrict__ Bh, const __nv_bfloat16* __restrict__ Bl,
             const float* __restrict__ bias, float* __restrict__ C,
             __nv_bfloat16* __restrict__ Ch, __nv_bfloat16* __restrict__ Cl,
             int N, int K) {
    extern __shared__ char smp[];
    const uint32_t sb = smem_u32(smp);

    const int tid = threadIdx.x;
    const int wid = tid >> 5;
    const int lane = tid & 31;
    const int wm = wid & 1;
    const int wn = wid >> 1;
    const int bm = blockIdx.y * 128;
    const int bn = blockIdx.x * 128;
    const int NKC = K >> 5;

    const int lrow0 = tid >> 2;
    const int lc16 = tid & 3;

    const int rowA = wm * 64 + (lane & 15);
    const int rowB = wn * 32 + (lane & 15);
    const int rswA = (rowA >> 1) & 3;
    const int rswB = (rowB >> 1) & 3;
    const int chalf = lane >> 4;

    float acc[4][4][4];
#pragma unroll
    for (int i = 0; i < 4; i++)
#pragma unroll
        for (int j = 0; j < 4; j++)
#pragma unroll
            for (int e = 0; e < 4; e++) acc[i][j][e] = 0.0f;

    auto load_stage = [&](int kc) {
        const uint32_t stg = sb + (uint32_t)(kc & 1) * STAGE_B;
        const int ke = kc * 32;
#pragma unroll
        for (int v = 0; v < 2; v++) {
            int row = lrow0 + v * 64;
            uint32_t swo = sw64(row, lc16);
            size_t ga = (size_t)(bm + row) * K + ke + lc16 * 8;
            size_t gb = (size_t)(bn + row) * K + ke + lc16 * 8;
            cpa16(stg + OFF_AH + swo, Ah + ga);
            cpa16(stg + OFF_AL + swo, Al + ga);
            cpa16(stg + OFF_BH + swo, Bh + gb);
            cpa16(stg + OFF_BL + swo, Bl + gb);
        }
    };

    load_stage(0);
    CPCOMMIT();

    for (int kc = 0; kc < NKC; kc++) {
        cpwait<0>();
        __syncthreads();
        // Prefetch next stage AFTER the sync: it overwrites the buffer whose
        // reads (iter kc-1) completed before this barrier.
        if (kc + 1 < NKC) {
            load_stage(kc + 1);
            CPCOMMIT();
        }

        const uint32_t stg = sb + (uint32_t)(kc & 1) * STAGE_B;
#pragma unroll
        for (int s16 = 0; s16 < 2; s16++) {
            const int c16 = s16 * 2 + chalf;
            const uint32_t aswc = (uint32_t)((c16 ^ rswA) * 16);
            const uint32_t bswc = (uint32_t)((c16 ^ rswB) * 16);

            uint32_t ah[4][4], al[4][4], bh[2][4], bl[2][4];
#pragma unroll
            for (int i = 0; i < 4; i++) {
                uint32_t ro = (uint32_t)((rowA + 16 * i) * 64);
                ldsm4(ah[i], stg + OFF_AH + ro + aswc);
                ldsm4(al[i], stg + OFF_AL + ro + aswc);
            }
#pragma unroll
            for (int g = 0; g < 2; g++) {
                uint32_t ro = (uint32_t)((rowB + 16 * g) * 64);
                ldsm4(bh[g], stg + OFF_BH + ro + bswc);
                ldsm4(bl[g], stg + OFF_BL + ro + bswc);
            }

            // term-major: same-accumulator reuse distance = 16 MMAs
#pragma unroll
            for (int i = 0; i < 4; i++)
#pragma unroll
                for (int g = 0; g < 2; g++)
#pragma unroll
                    for (int h = 0; h < 2; h++)
                        mma_bf16(acc[i][g * 2 + h], ah[i], bh[g][h], bh[g][h + 2]);
#pragma unroll
            for (int i = 0; i < 4; i++)
#pragma unroll
                for (int g = 0; g < 2; g++)
#pragma unroll
                    for (int h = 0; h < 2; h++)
                        mma_bf16(acc[i][g * 2 + h], ah[i], bl[g][h], bl[g][h + 2]);
#pragma unroll
            for (int i = 0; i < 4; i++)
#pragma unroll
                for (int g = 0; g < 2; g++)
#pragma unroll
                    for (int h = 0; h < 2; h++)
                        mma_bf16(acc[i][g * 2 + h], al[i], bh[g][h], bh[g][h + 2]);
        }
    }

    const int lane4 = lane >> 2;
    const int lm2 = (lane & 3) * 2;
#pragma unroll
    for (int i = 0; i < 4; i++) {
        int r0 = bm + wm * 64 + i * 16 + lane4;
#pragma unroll
        for (int j = 0; j < 4; j++) {
            int cc = bn + wn * 32 + j * 8 + lm2;
            float b0 = bias[cc], b1 = bias[cc + 1];
            float v00 = acc[i][j][0] + b0, v01 = acc[i][j][1] + b1;
            float v10 = acc[i][j][2] + b0, v11 = acc[i][j][3] + b1;
            if (SPLIT_OUT) {
                __nv_bfloat16 h0, l0, h1, l1;
                split_bf16(v00, h0, l0);
                split_bf16(v01, h1, l1);
                __nv_bfloat162 ph = {h0, h1}, pl = {l0, l1};
                *(uint32_t*)&Ch[(size_t)r0 * N + cc] = *(uint32_t*)&ph;
                *(uint32_t*)&Cl[(size_t)r0 * N + cc] = *(uint32_t*)&pl;
                split_bf16(v10, h0, l0);
                split_bf16(v11, h1, l1);
                __nv_bfloat162 qh = {h0, h1}, ql = {l0, l1};
                *(uint32_t*)&Ch[(size_t)(r0 + 8) * N + cc] = *(uint32_t*)&qh;
                *(uint32_t*)&Cl[(size_t)(r0 + 8) * N + cc] = *(uint32_t*)&ql;
            } else {
                *(float2*)&C[(size_t)r0 * N + cc] = {v00, v01};
                *(float2*)&C[(size_t)(r0 + 8) * N + cc] = {v10, v11};
            }
        }
    }
}

// ---------------------------------------------------------------------------
// Tensor-core causal flash attention (term-major MMA ordering).
// ---------------------------------------------------------------------------
#define AOFF_QH 0
#define AOFF_QL 16384
#define AOFF_KV 32768
#define ASTG 32768
#define AOFF_KH 0
#define AOFF_KL 8192
#define AOFF_VH 16384
#define AOFF_VL 24576
#define ATT_SMEM (AOFF_KV + 2 * ASTG)   // 98304

__device__ __forceinline__ uint32_t asw(int row, int c16) {
    return (uint32_t)(row * 128 + ((c16 ^ (row & 7)) * 16));
}

__global__ __launch_bounds__(256)
void attn_tc(const __nv_bfloat16* __restrict__ qh,
             const __nv_bfloat16* __restrict__ ql,
             __nv_bfloat16* __restrict__ oh, __nv_bfloat16* __restrict__ ol) {
    extern __shared__ char smp[];
    const uint32_t sb = smem_u32(smp);

    const int tid = threadIdx.x;
    const int wid = tid >> 5;
    const int lane = tid & 31;
    const int bh = blockIdx.y;
    const int b = bh / NHz;
    const int h = bh % NHz;
    const int q0 = blockIdx.x * 128;

    const __nv_bfloat16* qbh = qh + (size_t)b * Tz * N_QKV + h * HDz;
    const __nv_bfloat16* qbl = ql + (size_t)b * Tz * N_QKV + h * HDz;

    // ---- load Q tile (hi+lo) ----
#pragma unroll
    for (int i = 0; i < 4; i++) {
        int idx = tid + i * 256;
        int row = idx >> 3;
        int c = idx & 7;
        uint32_t swo = asw(row, c);
        size_t g = (size_t)(q0 + row) * N_QKV + c * 8;
        cpa16(sb + AOFF_QH + swo, qbh + g);
        cpa16(sb + AOFF_QL + swo, qbl + g);
    }
    CPCOMMIT();

    auto load_kv = [&](int kt) {
        const uint32_t stg = sb + AOFF_KV + (uint32_t)(kt & 1) * ASTG;
        const int k0 = kt * 64;
#pragma unroll
        for (int v = 0; v < 2; v++) {
            int row = (tid >> 3) + v * 32;
            int c = tid & 7;
            uint32_t swo = asw(row, c);
            size_t g = (size_t)(k0 + row) * N_QKV + c * 8;
            cpa16(stg + AOFF_KH + swo, qbh + g + Cz);
            cpa16(stg + AOFF_KL + swo, qbl + g + Cz);
            cpa16(stg + AOFF_VH + swo, qbh + g + 2 * Cz);
            cpa16(stg + AOFF_VL + swo, qbl + g + 2 * Cz);
        }
    };

    load_kv(0);
    CPCOMMIT();
    cpwait<1>();        // Q arrived
    __syncthreads();

    const int rowQ = wid * 16 + (lane & 15);
    const int chalf = lane >> 4;
    const int grp = lane >> 2;          // row-in-16 (lo); hi = +8
    const int lm2 = (lane & 3) * 2;

    float oacc[8][4];
#pragma unroll
    for (int nf = 0; nf < 8; nf++)
#pragma unroll
        for (int e = 0; e < 4; e++) oacc[nf][e] = 0.0f;
    float mrow[2] = {-1e30f, -1e30f};
    float lrow[2] = {0.0f, 0.0f};

    const int ntiles = (q0 + 128) / 64;
    for (int kt = 0; kt < ntiles; kt++) {
        if (kt + 1 < ntiles) {
            load_kv(kt + 1);
            CPCOMMIT();
            cpwait<1>();
        } else {
            cpwait<0>();
        }
        __syncthreads();

        const uint32_t stg = sb + AOFF_KV + (uint32_t)(kt & 1) * ASTG;
        const int k0 = kt * 64;

        // ---- S = Q K^T (3-term, term-major over 8 accumulators) ----
        float sacc[8][4];
#pragma unroll
        for (int nf = 0; nf < 8; nf++)
#pragma unroll
            for (int e = 0; e < 4; e++) sacc[nf][e] = 0.0f;

#pragma unroll
        for (int kc = 0; kc < 4; kc++) {
            int c16 = kc * 2 + chalf;
            uint32_t qad = (uint32_t)(rowQ * 128 + ((c16 ^ (rowQ & 7)) * 16));
            uint32_t qfh[4], qfl[4];
            ldsm4(qfh, sb + AOFF_QH + qad);
            ldsm4(qfl, sb + AOFF_QL + qad);

            uint32_t kh[4][4], kl[4][4];
#pragma unroll
            for (int g = 0; g < 4; g++) {
                int rowK = g * 16 + (lane & 15);
                uint32_t ad = (uint32_t)(rowK * 128 + ((c16 ^ (rowK & 7)) * 16));
                ldsm4(kh[g], stg + AOFF_KH + ad);
                ldsm4(kl[g], stg + AOFF_KL + ad);
            }
#pragma unroll
            for (int g = 0; g < 4; g++)
#pragma unroll
                for (int hh = 0; hh < 2; hh++)
                    mma_bf16(sacc[g * 2 + hh], qfh, kh[g][hh], kh[g][hh + 2]);
#pragma unroll
            for (int g = 0; g < 4; g++)
#pragma unroll
                for (int hh = 0; hh < 2; hh++)
                    mma_bf16(sacc[g * 2 + hh], qfh, kl[g][hh], kl[g][hh + 2]);
#pragma unroll
            for (int g = 0; g < 4; g++)
#pragma unroll
                for (int hh = 0; hh < 2; hh++)
                    mma_bf16(sacc[g * 2 + hh], qfl, kh[g][hh], kh[g][hh + 2]);
        }

        // ---- scale + causal mask ----
        const bool domask = (k0 + 63 > q0);
#pragma unroll
        for (int nf = 0; nf < 8; nf++)
#pragma unroll
            for (int e = 0; e < 4; e++) {
                float s = sacc[nf][e] * 0.125f;
                if (domask) {
                    int kcol = k0 + nf * 8 + lm2 + (e & 1);
                    int qrow = q0 + wid * 16 + grp + ((e >> 1) << 3);
                    if (kcol > qrow) s = -1e30f;
                }
                sacc[nf][e] = s;
            }

        // ---- online softmax ----
#pragma unroll
        for (int r = 0; r < 2; r++) {
            float mt = -1e30f;
#pragma unroll
            for (int nf = 0; nf < 8; nf++)
                mt = fmaxf(mt, fmaxf(sacc[nf][2 * r], sacc[nf][2 * r + 1]));
            mt = fmaxf(mt, __shfl_xor_sync(0xffffffffu, mt, 1));
            mt = fmaxf(mt, __shfl_xor_sync(0xffffffffu, mt, 2));
            float mnew = fmaxf(mrow[r], mt);
            float alpha = __expf(mrow[r] - mnew);
            float ls = 0.0f;
#pragma unroll
            for (int nf = 0; nf < 8; nf++) {
                float p0 = __expf(sacc[nf][2 * r] - mnew);
                float p1 = __expf(sacc[nf][2 * r + 1] - mnew);
                sacc[nf][2 * r] = p0;
                sacc[nf][2 * r + 1] = p1;
                ls += p0 + p1;
            }
            ls += __shfl_xor_sync(0xffffffffu, ls, 1);
            ls += __shfl_xor_sync(0xffffffffu, ls, 2);
            lrow[r] = lrow[r] * alpha + ls;
            mrow[r] = mnew;
#pragma unroll
            for (int nf = 0; nf < 8; nf++) {
                oacc[nf][2 * r] *= alpha;
                oacc[nf][2 * r + 1] *= alpha;
            }
        }

        // ---- P -> split bf16 A-fragments (in-register) ----
        uint32_t pfh[4][4], pfl[4][4];
#pragma unroll
        for (int kc = 0; kc < 4; kc++) {
#pragma unroll
            for (int part = 0; part < 4; part++) {
                int nf = kc * 2 + (part >> 1);
                int e = (part & 1) * 2;
                float p0 = sacc[nf][e], p1 = sacc[nf][e + 1];
                __nv_bfloat16 h0, l0, h1, l1;
                split_bf16(p0, h0, l0);
                split_bf16(p1, h1, l1);
                __nv_bfloat162 vh2 = {h0, h1}, vl2 = {l0, l1};
                pfh[kc][part] = *(uint32_t*)&vh2;
                pfl[kc][part] = *(uint32_t*)&vl2;
            }
        }

        // ---- O += P V (3-term, term-major over 8 accumulators per kc) ----
#pragma unroll
        for (int kc = 0; kc < 4; kc++) {
            uint32_t vh[4][4], vl[4][4];
#pragma unroll
            for (int idx = 0; idx < 4; idx++) {
                int vg = idx >> 1, half = idx & 1;
                int rowV = kc * 16 + (lane & 7) + ((lane >> 3) & 1) * 8;
                int c16 = vg * 4 + half * 2 + (lane >> 4);
                uint32_t ad = (uint32_t)(rowV * 128 + ((c16 ^ (rowV & 7)) * 16));
                ldsm4t(vh[idx], stg + AOFF_VH + ad);
                ldsm4t(vl[idx], stg + AOFF_VL + ad);
            }
#pragma unroll
            for (int idx = 0; idx < 4; idx++) {
                int nf0 = (idx >> 1) * 4 + (idx & 1) * 2;
                mma_bf16(oacc[nf0], pfh[kc], vh[idx][0], vh[idx][1]);
                mma_bf16(oacc[nf0 + 1], pfh[kc], vh[idx][2], vh[idx][3]);
            }
#pragma unroll
            for (int idx = 0; idx < 4; idx++) {
                int nf0 = (idx >> 1) * 4 + (idx & 1) * 2;
                mma_bf16(oacc[nf0], pfh[kc], vl[idx][0], vl[idx][1]);
                mma_bf16(oacc[nf0 + 1], pfh[kc], vl[idx][2], vl[idx][3]);
            }
#pragma unroll
            for (int idx = 0; idx < 4; idx++) {
                int nf0 = (idx >> 1) * 4 + (idx & 1) * 2;
                mma_bf16(oacc[nf0], pfl[kc], vh[idx][0], vh[idx][1]);
                mma_bf16(oacc[nf0 + 1], pfl[kc], vh[idx][2], vh[idx][3]);
            }
        }
        __syncthreads();
    }

    // ---- epilogue: normalize, split, store bf16 hi/lo ----
#pragma unroll
    for (int r = 0; r < 2; r++) {
        float inv = 1.0f / lrow[r];
        size_t row = (size_t)(b * Tz + q0 + wid * 16 + grp + r * 8);
#pragma unroll
        for (int nf = 0; nf < 8; nf++) {
            float v0 = oacc[nf][2 * r] * inv;
            float v1 = oacc[nf][2 * r + 1] * inv;
            __nv_bfloat16 h0, l0, h1, l1;
            split_bf16(v0, h0, l0);
            split_bf16(v1, h1, l1);
            __nv_bfloat162 ph = {h0, h1}, pl = {l0, l1};
            size_t o = row * Cz + h * HDz + nf * 8 + lm2;
            *(uint32_t*)&oh[o] = *(uint32_t*)&ph;
            *(uint32_t*)&ol[o] = *(uint32_t*)&pl;
        }
    }
}

// ---------------------------------------------------------------------------
// Launch
// ---------------------------------------------------------------------------
extern "C" void kernel_launch(void* const* d_in, const int* in_sizes, int n_in,
                              void* d_out, int out_size) {
    const float* x      = (const float*)d_in[0];
    const float* W_attn = (const float*)d_in[1];
    const float* b_attn = (const float*)d_in[2];
    const float* W_proj = (const float*)d_in[3];
    const float* b_proj = (const float*)d_in[4];
    float* out = (float*)d_out;

    __nv_bfloat16 *xh, *xl, *qkvh, *qkvl, *ath, *atl, *wah, *wal, *wph, *wpl;
    cudaGetSymbolAddress((void**)&xh, g_xh);
    cudaGetSymbolAddress((void**)&xl, g_xl);
    cudaGetSymbolAddress((void**)&qkvh, g_qkvh);
    cudaGetSymbolAddress((void**)&qkvl, g_qkvl);
    cudaGetSymbolAddress((void**)&ath, g_ath);
    cudaGetSymbolAddress((void**)&atl, g_atl);
    cudaGetSymbolAddress((void**)&wah, g_wah);
    cudaGetSymbolAddress((void**)&wal, g_wal);
    cudaGetSymbolAddress((void**)&wph, g_wph);
    cudaGetSymbolAddress((void**)&wpl, g_wpl);

    cudaFuncSetAttribute(tc_gemm<true>, cudaFuncAttributeMaxDynamicSharedMemorySize, GEMM_SMEM);
    cudaFuncSetAttribute(tc_gemm<false>, cudaFuncAttributeMaxDynamicSharedMemorySize, GEMM_SMEM);
    cudaFuncSetAttribute(attn_tc, cudaFuncAttributeMaxDynamicSharedMemorySize, ATT_SMEM);

    const int n4 = Mz * Cz / 4;

    split_kernel<<<n4 / 256, 256>>>(x, xh, xl, n4);
    tsplit_kernel<<<dim3(N_QKV / 32, Cz / 32), dim3(32, 8)>>>(W_attn, wah, wal, Cz, N_QKV);
    tsplit_kernel<<<dim3(Cz / 32, Cz / 32), dim3(32, 8)>>>(W_proj, wph, wpl, Cz, Cz);

    // 1) QKV projection -> split bf16 output
    tc_gemm<true><<<dim3(N_QKV / 128, Mz / 128), 256, GEMM_SMEM>>>(
        xh, xl, wah, wal, b_attn, nullptr, qkvh, qkvl, N_QKV, Cz);

    // 2) Tensor-core causal attention -> split bf16 output
    attn_tc<<<dim3(Tz / 128, Bz * NHz), 256, ATT_SMEM>>>(qkvh, qkvl, ath, atl);

    // 3) Output projection -> fp32
    tc_gemm<false><<<dim3(Cz / 128, Mz / 128), 256, GEMM_SMEM>>>(
        ath, atl, wph, wpl, b_proj, out, nullptr, nullptr, Cz, Cz);
}